// round 3
// baseline (speedup 1.0000x reference)
#include <cuda_runtime.h>
#include <math.h>

typedef unsigned long long ull;

#define S_LEN 256
#define T_LEN 256
#define BATCH 32
#define DIN   2048
#define HID   1024
#define G4    4096
#define MROWS (S_LEN * BATCH)          // 8192

// ---------------- static device scratch (no runtime allocation) ----------------
__device__ float  g_xW[MROWS * G4];            // 128 MiB gate pre-activations (recurrence layout)
__device__ float  g_out2[MROWS * HID];         // layer-2 output [s][b][j]
__device__ float  g_out3[MROWS * HID];         // layer-3 output [s][b][j]
__device__ float  g_h[2][BATCH * HID];         // DOUBLE-BUFFERED recurrent h state (L2-coherent)
__device__ float4 g_Wt2[(HID / 4) * G4];       // lane-transposed Whh per layer: [k4][g']
__device__ float4 g_Wt3[(HID / 4) * G4];
__device__ float4 g_Wt4v[(HID / 4) * G4];
__device__ unsigned g_bar_count;
__device__ volatile unsigned g_bar_gen;

// ---------------- packed fp32x2 helpers (2x FFMA throughput on sm_103a) ----------------
__device__ __forceinline__ void fma2(ull &acc, ull a, ull b) {
    asm("fma.rn.f32x2 %0, %1, %2, %0;" : "+l"(acc) : "l"(a), "l"(b));
}
__device__ __forceinline__ float2 upk2(ull v) {
    float2 f; asm("mov.b64 {%0, %1}, %2;" : "=f"(f.x), "=f"(f.y) : "l"(v)); return f;
}
__device__ __forceinline__ float sigm(float x) { return 1.0f / (1.0f + expf(-x)); }

// ---------------- grid-wide sense barrier (all blocks co-resident: 1 block/SM) ----------------
__device__ __forceinline__ void grid_sync(int nblk) {
    __syncthreads();
    if (threadIdx.x == 0) {
        __threadfence();
        unsigned gen = g_bar_gen;
        if (atomicAdd(&g_bar_count, 1u) == (unsigned)(nblk - 1)) {
            g_bar_count = 0;
            __threadfence();
            g_bar_gen = gen + 1u;
        } else {
            while (g_bar_gen == gen) { __nanosleep(20); }
        }
        __threadfence();
    }
    __syncthreads();
}

// ---------------- Whh transpose: Wt[k4][g'] = {Whh[g][4k4..4k4+3]} ----------------
// g = q*1024 + jgrp*8 + jj ;  g' = jgrp*32 + q*8 + jj   (block-contiguous gate rows)
__global__ void wtrans_kernel(const float* __restrict__ W, int which) {
    float4* dst = (which == 0) ? g_Wt2 : (which == 1) ? g_Wt3 : g_Wt4v;
    int idx = blockIdx.x * 256 + threadIdx.x;          // [0, 1048576)
    int k4 = idx >> 12;
    int gp = idx & 4095;
    int jgrp = gp >> 5;
    int r    = gp & 31;
    int q    = r >> 3;
    int jj   = r & 7;
    int g = q * HID + jgrp * 8 + jj;
    dst[idx] = *(const float4*)(W + (size_t)g * HID + k4 * 4);
}

// ---------------- zero the h state (buffer 0 only; step 0 reads buf 0) ----------------
__global__ void zeroh_kernel() {
    g_h[0][blockIdx.x * 256 + threadIdx.x] = 0.0f;
}

// ---------------- GEMM: g_xW = (A .* mask) @ W^T + (bih+bhh), recurrence layout ------------
// A rows are m = s*32+b, lda = K. BM=128, BN=64, BK=16, 256 threads, 8x4 microtile,
// f32x2 accumulation over (even k, odd k).
__global__ void __launch_bounds__(256) gemm_kernel(
    const float* __restrict__ Aext, int asel,
    const float* __restrict__ W,
    const float* __restrict__ mask,
    const float* __restrict__ bih, const float* __restrict__ bhh,
    int K)
{
    __shared__ float As[128 * 20];
    __shared__ float Bs[64 * 20];
    const float* A = (asel == 0) ? Aext : (asel == 1) ? g_out2 : g_out3;

    int tid = threadIdx.x;
    int mBase = blockIdx.y * 128;
    int nBase = blockIdx.x * 64;
    int tm = tid >> 4;     // 0..15
    int tn = tid & 15;     // 0..15

    ull acc[8][4];
#pragma unroll
    for (int i = 0; i < 8; ++i)
#pragma unroll
        for (int j = 0; j < 4; ++j) acc[i][j] = 0ull;

    for (int kt = 0; kt < K; kt += 16) {
        // load A tile: 512 float4, 2 per thread
#pragma unroll
        for (int u = 0; u < 2; ++u) {
            int v = tid + u * 256;
            int row = v >> 2, c4 = v & 3;
            float4 av = *(const float4*)(A + (size_t)(mBase + row) * K + kt + c4 * 4);
            if (mask) {
                float4 mv = *(const float4*)(mask + (size_t)(mBase + row) * K + kt + c4 * 4);
                av.x *= mv.x; av.y *= mv.y; av.z *= mv.z; av.w *= mv.w;
            }
            *(float4*)(As + row * 20 + c4 * 4) = av;
        }
        // load B tile: 256 float4, 1 per thread
        {
            int row = tid >> 2, c4 = tid & 3;
            float4 bv = *(const float4*)(W + (size_t)(nBase + row) * K + kt + c4 * 4);
            *(float4*)(Bs + row * 20 + c4 * 4) = bv;
        }
        __syncthreads();
#pragma unroll
        for (int kk = 0; kk < 16; kk += 4) {
            ulonglong2 b2[4];
#pragma unroll
            for (int j = 0; j < 4; ++j)
                b2[j] = *(const ulonglong2*)(Bs + (tn + j * 16) * 20 + kk);
#pragma unroll
            for (int i = 0; i < 8; ++i) {
                ulonglong2 a2 = *(const ulonglong2*)(As + (tm + i * 16) * 20 + kk);
#pragma unroll
                for (int j = 0; j < 4; ++j) {
                    fma2(acc[i][j], a2.x, b2[j].x);
                    fma2(acc[i][j], a2.y, b2[j].y);
                }
            }
        }
        __syncthreads();
    }

    // epilogue: fold bias, write recurrence layout [s][jgrp][q][jj][b]
#pragma unroll
    for (int j = 0; j < 4; ++j) {
        int g = nBase + tn + j * 16;
        float bsum = bih[g] + bhh[g];
        int q = g >> 10, j1 = g & 1023, jgrp = j1 >> 3, jjx = j1 & 7;
#pragma unroll
        for (int i = 0; i < 8; ++i) {
            int m = mBase + tm + i * 16;
            int s = m >> 5, b = m & 31;
            float2 p = upk2(acc[i][j]);
            g_xW[(size_t)(s * 128 + jgrp) * 1024 + q * 256 + jjx * 32 + b] = p.x + p.y + bsum;
        }
    }
}

// ---------------- persistent recurrence kernel (256 steps, grid-synced) ----------------
// 128 blocks x 256 threads, 1 block/SM (smem-limited). Block bid owns j in [bid*8, bid*8+8).
// Compute phase: thread (r=tid&31, bgrp=tid>>5): gate-row g'=bid*32+r, 4 batches.
// Update phase: thread (jj=tid>>5, b=tid&31): owns cell (j=bid*8+jj, b); c in register.
// h state is DOUBLE-BUFFERED across steps: step t reads g_h[t&1], writes g_h[(t&1)^1],
// so the per-step read phase and write phase touch disjoint buffers (no intra-step race);
// the single grid_sync at the end of each step orders write(t) before read(t+1).
#define REC_SMEM (32 * 1024 * 4 + 32 * 33 * 4)

__global__ void __launch_bounds__(256, 1) rec_kernel(int layer, float* __restrict__ dout) {
    extern __shared__ float sm[];
    float* hs = sm;              // [32][1024]
    float* gs = sm + 32768;      // [32][33] padded

    const float4* Wt  = (layer == 0) ? g_Wt2 : (layer == 1) ? g_Wt3 : g_Wt4v;
    const float*  res = (layer == 0) ? (const float*)0 : (layer == 1) ? g_out2 : g_out3;
    float*        out = (layer == 0) ? g_out2 : (layer == 1) ? g_out3 : dout;

    int tid = threadIdx.x, bid = blockIdx.x;
    int r = tid & 31, bgrp = tid >> 5;
    int jj = tid >> 5, bu = tid & 31;
    int nblk = gridDim.x;

    const float4* wp = Wt + (bid * 32 + r);
    const ulonglong2* hp0 = (const ulonglong2*)(hs + (bgrp * 4 + 0) * HID);
    const ulonglong2* hp1 = (const ulonglong2*)(hs + (bgrp * 4 + 1) * HID);
    const ulonglong2* hp2 = (const ulonglong2*)(hs + (bgrp * 4 + 2) * HID);
    const ulonglong2* hp3 = (const ulonglong2*)(hs + (bgrp * 4 + 3) * HID);

    float c = 0.0f;

    for (int t = 0; t < S_LEN; ++t) {
        // ---- fill hs from L2-coherent read buffer g_h[t&1] ----
        {
            const float4* gh4 = (const float4*)g_h[t & 1];
            float4* hs4 = (float4*)hs;
#pragma unroll
            for (int i = 0; i < 32; ++i)
                hs4[tid + i * 256] = __ldcg(gh4 + tid + i * 256);
        }
        __syncthreads();

        // ---- dot products: gate[g', b] = sum_k Whh[g][k] * h[b][k] ----
        ull a0 = 0ull, a1 = 0ull, a2 = 0ull, a3 = 0ull;
#pragma unroll 8
        for (int k4 = 0; k4 < 256; ++k4) {
            ulonglong2 w = *(const ulonglong2*)(wp + (size_t)k4 * 4096);
            ulonglong2 x0 = hp0[k4];
            ulonglong2 x1 = hp1[k4];
            ulonglong2 x2 = hp2[k4];
            ulonglong2 x3 = hp3[k4];
            fma2(a0, w.x, x0.x); fma2(a0, w.y, x0.y);
            fma2(a1, w.x, x1.x); fma2(a1, w.y, x1.y);
            fma2(a2, w.x, x2.x); fma2(a2, w.y, x2.y);
            fma2(a3, w.x, x3.x); fma2(a3, w.y, x3.y);
        }
        {
            float2 p;
            p = upk2(a0); gs[(bgrp * 4 + 0) * 33 + r] = p.x + p.y;
            p = upk2(a1); gs[(bgrp * 4 + 1) * 33 + r] = p.x + p.y;
            p = upk2(a2); gs[(bgrp * 4 + 2) * 33 + r] = p.x + p.y;
            p = upk2(a3); gs[(bgrp * 4 + 3) * 33 + r] = p.x + p.y;
        }
        __syncthreads();

        // ---- cell update: thread owns (j = bid*8+jj, b = bu); write buffer g_h[(t&1)^1] ----
        {
            int base = (t * 128 + bid) * 1024 + jj * 32 + bu;  // xW' [s][jgrp][q][jj][b]
            float gi = gs[bu * 33 + 0 + jj] + g_xW[base];
            float gf = gs[bu * 33 + 8 + jj] + g_xW[base + 256];
            float gg = gs[bu * 33 + 16 + jj] + g_xW[base + 512];
            float go = gs[bu * 33 + 24 + jj] + g_xW[base + 768];
            c = sigm(gf) * c + sigm(gi) * tanhf(gg);
            float h = sigm(go) * tanhf(c);
            int jglob = bid * 8 + jj;
            __stcg(&g_h[(t & 1) ^ 1][bu * HID + jglob], h);
            size_t oidx = (size_t)(t * 32 + bu) * HID + jglob;
            out[oidx] = res ? (h + res[oidx]) : h;
        }
        grid_sync(nblk);
    }
}

// ---------------- output assembly ----------------
__global__ void header_kernel(float* __restrict__ out) {
    int idx = blockIdx.x * 256 + threadIdx.x;   // [0, 32768)
    float v = 0.0f;
    if (idx == 0) v = 513.0f;        // 1 + s + t
    else if (idx == 1) v = 257.0f;   // s + 1
    else if (idx == 2) v = 258.0f;   // s + 2
    else if (idx == 3) v = 513.0f;   // t + s + 1
    out[idx] = v;
}

__global__ void srccopy_kernel(const float* __restrict__ in, float* __restrict__ out) {
    int idx = blockIdx.x * 256 + threadIdx.x;   // [0, 2097152) float4
    int tt  = idx >> 13;
    int rem = idx & 8191;
    int b   = rem >> 8;
    int j4  = rem & 255;
    const float4* i4 = (const float4*)in;
    float4* o4 = (float4*)out;
    o4[(size_t)(257 + tt) * 8192 + rem] =
        i4[(size_t)(257 + tt) * 16384 + b * 512 + j4];
}

// ---------------- launch ----------------
extern "C" void kernel_launch(void* const* d_in, const int* in_sizes, int n_in,
                              void* d_out, int out_size) {
    const float* input = (const float*)d_in[0];
    const float* Wih2  = (const float*)d_in[1];
    const float* Whh2  = (const float*)d_in[2];
    const float* bih2  = (const float*)d_in[3];
    const float* bhh2  = (const float*)d_in[4];
    const float* Wih3  = (const float*)d_in[5];
    const float* Whh3  = (const float*)d_in[6];
    const float* bih3  = (const float*)d_in[7];
    const float* bhh3  = (const float*)d_in[8];
    const float* Wih4  = (const float*)d_in[9];
    const float* Whh4  = (const float*)d_in[10];
    const float* bih4  = (const float*)d_in[11];
    const float* bhh4  = (const float*)d_in[12];
    const float* mask2 = (const float*)d_in[13];
    const float* mask3 = (const float*)d_in[14];
    float* out = (float*)d_out;

    cudaFuncSetAttribute(rec_kernel, cudaFuncAttributeMaxDynamicSharedMemorySize, REC_SMEM);

    // weight transposes + independent output pieces
    wtrans_kernel<<<4096, 256>>>(Whh2, 0);
    wtrans_kernel<<<4096, 256>>>(Whh3, 1);
    wtrans_kernel<<<4096, 256>>>(Whh4, 2);
    header_kernel<<<128, 256>>>(out);
    srccopy_kernel<<<8192, 256>>>(input, out);

    dim3 ggrid(64, 64);

    // layer 2: A = input[1:257] (lda = 2048), no mask
    gemm_kernel<<<ggrid, 256>>>(input + BATCH * DIN, 0, Wih2, (const float*)0, bih2, bhh2, DIN);
    zeroh_kernel<<<128, 256>>>();
    rec_kernel<<<128, 256, REC_SMEM>>>(0, (float*)0);

    // layer 3: A = out2 * mask2
    gemm_kernel<<<ggrid, 256>>>((const float*)0, 1, Wih3, mask2, bih3, bhh3, HID);
    zeroh_kernel<<<128, 256>>>();
    rec_kernel<<<128, 256, REC_SMEM>>>(1, (float*)0);

    // layer 4: A = out3 * mask3; writes rows 1..256 of the output directly
    gemm_kernel<<<ggrid, 256>>>((const float*)0, 2, Wih4, mask3, bih4, bhh4, HID);
    zeroh_kernel<<<128, 256>>>();
    rec_kernel<<<128, 256, REC_SMEM>>>(2, out + BATCH * HID);
}

// round 16
// speedup vs baseline: 1.2563x; 1.2563x over previous
#include <cuda_runtime.h>
#include <cuda_bf16.h>
#include <math.h>
#include <stdint.h>

typedef unsigned long long ull;

#define S_LEN 256
#define T_LEN 256
#define BATCH 32
#define DIN   2048
#define HID   1024
#define G4    4096
#define MROWS (S_LEN * BATCH)          // 8192

// ---------------- static device scratch (no runtime allocation) ----------------
__device__ float  g_xW[MROWS * G4];            // gate pre-activations (recurrence layout)
__device__ float  g_out2[MROWS * HID];
__device__ float  g_out3[MROWS * HID];
__device__ float  g_h[2][BATCH * HID];         // double-buffered recurrent h state
__device__ float4 g_Wt2[(HID / 4) * G4];       // lane-transposed Whh per layer
__device__ float4 g_Wt3[(HID / 4) * G4];
__device__ float4 g_Wt4v[(HID / 4) * G4];
__device__ unsigned g_bar_count;
__device__ volatile unsigned g_bar_gen;

// bf16 hi/lo operands for the tensor-core GEMMs (reused across layers)
__device__ __nv_bfloat16 g_Ahi[MROWS * DIN];
__device__ __nv_bfloat16 g_Alo[MROWS * DIN];
__device__ __nv_bfloat16 g_Whi[G4 * DIN];
__device__ __nv_bfloat16 g_Wlo[G4 * DIN];

// ---------------- packed fp32x2 helpers ----------------
__device__ __forceinline__ void fma2(ull &acc, ull a, ull b) {
    asm("fma.rn.f32x2 %0, %1, %2, %0;" : "+l"(acc) : "l"(a), "l"(b));
}
__device__ __forceinline__ float2 upk2(ull v) {
    float2 f; asm("mov.b64 {%0, %1}, %2;" : "=f"(f.x), "=f"(f.y) : "l"(v)); return f;
}
__device__ __forceinline__ float sigm(float x) { return 1.0f / (1.0f + expf(-x)); }

// ---------------- smem / mma helpers (baseline PTX only — no 'a' features) ----------------
__device__ __forceinline__ uint32_t smem_u32(const void* p) {
    uint32_t a;
    asm("{ .reg .u64 t; cvta.to.shared.u64 t, %1; cvt.u32.u64 %0, t; }" : "=r"(a) : "l"(p));
    return a;
}
__device__ __forceinline__ void cpa16(uint32_t dst, const void* src) {
    asm volatile("cp.async.cg.shared.global [%0], [%1], 16;" :: "r"(dst), "l"(src));
}
__device__ __forceinline__ void ldm4(uint32_t r[4], uint32_t addr) {
    asm volatile("ldmatrix.sync.aligned.m8n8.x4.shared.b16 {%0,%1,%2,%3}, [%4];"
        : "=r"(r[0]), "=r"(r[1]), "=r"(r[2]), "=r"(r[3]) : "r"(addr));
}
__device__ __forceinline__ void mma_bf16(float c[4], const uint32_t a[4],
                                         uint32_t b0, uint32_t b1) {
    asm volatile(
        "mma.sync.aligned.m16n8k16.row.col.f32.bf16.bf16.f32 "
        "{%0,%1,%2,%3},{%4,%5,%6,%7},{%8,%9},{%0,%1,%2,%3};"
        : "+f"(c[0]), "+f"(c[1]), "+f"(c[2]), "+f"(c[3])
        : "r"(a[0]), "r"(a[1]), "r"(a[2]), "r"(a[3]), "r"(b0), "r"(b1));
}

// ---------------- grid-wide sense barrier ----------------
__device__ __forceinline__ void grid_sync(int nblk) {
    __syncthreads();
    if (threadIdx.x == 0) {
        __threadfence();
        unsigned gen = g_bar_gen;
        if (atomicAdd(&g_bar_count, 1u) == (unsigned)(nblk - 1)) {
            g_bar_count = 0;
            __threadfence();
            g_bar_gen = gen + 1u;
        } else {
            while (g_bar_gen == gen) { __nanosleep(20); }
        }
        __threadfence();
    }
    __syncthreads();
}

// ---------------- Whh transpose for the SIMT recurrence ----------------
__global__ void wtrans_kernel(const float* __restrict__ W, int which) {
    float4* dst = (which == 0) ? g_Wt2 : (which == 1) ? g_Wt3 : g_Wt4v;
    int idx = blockIdx.x * 256 + threadIdx.x;
    int k4 = idx >> 12;
    int gp = idx & 4095;
    int jgrp = gp >> 5;
    int r    = gp & 31;
    int q    = r >> 3;
    int jj   = r & 7;
    int g = q * HID + jgrp * 8 + jj;
    dst[idx] = *(const float4*)(W + (size_t)g * HID + k4 * 4);
}

__global__ void zeroh_kernel() {
    g_h[0][blockIdx.x * 256 + threadIdx.x] = 0.0f;
}

// ---------------- fp32 -> bf16 hi/lo split kernels ----------------
__device__ __forceinline__ void split4(float4 v, uint2 &hi, uint2 &lo) {
    __nv_bfloat16 hx = __float2bfloat16(v.x), hy = __float2bfloat16(v.y);
    __nv_bfloat16 hz = __float2bfloat16(v.z), hw = __float2bfloat16(v.w);
    __nv_bfloat16 lx = __float2bfloat16(v.x - __bfloat162float(hx));
    __nv_bfloat16 ly = __float2bfloat16(v.y - __bfloat162float(hy));
    __nv_bfloat16 lz = __float2bfloat16(v.z - __bfloat162float(hz));
    __nv_bfloat16 lw = __float2bfloat16(v.w - __bfloat162float(hw));
    hi.x = ((uint32_t)__bfloat16_as_ushort(hy) << 16) | __bfloat16_as_ushort(hx);
    hi.y = ((uint32_t)__bfloat16_as_ushort(hw) << 16) | __bfloat16_as_ushort(hz);
    lo.x = ((uint32_t)__bfloat16_as_ushort(ly) << 16) | __bfloat16_as_ushort(lx);
    lo.y = ((uint32_t)__bfloat16_as_ushort(lw) << 16) | __bfloat16_as_ushort(lz);
}

__global__ void convA_kernel(int asel, const float4* __restrict__ ext,
                             const float4* __restrict__ mask, int n4) {
    int i = blockIdx.x * 256 + threadIdx.x;
    if (i >= n4) return;
    const float4* src = (asel == 0) ? ext
                      : (asel == 1) ? (const float4*)g_out2 : (const float4*)g_out3;
    float4 v = src[i];
    if (mask) {
        float4 m = mask[i];
        v.x *= m.x; v.y *= m.y; v.z *= m.z; v.w *= m.w;
    }
    uint2 hi, lo;
    split4(v, hi, lo);
    ((uint2*)g_Ahi)[i] = hi;
    ((uint2*)g_Alo)[i] = lo;
}

__global__ void convW_kernel(const float4* __restrict__ W, int n4) {
    int i = blockIdx.x * 256 + threadIdx.x;
    if (i >= n4) return;
    uint2 hi, lo;
    split4(W[i], hi, lo);
    ((uint2*)g_Whi)[i] = hi;
    ((uint2*)g_Wlo)[i] = lo;
}

// ---------------- mma.sync GEMM: g_xW = [Ahi|Alo] x [Whi|Wlo]^T (3-pass) + bias ----------
// CTA tile: M=128 x N=64, BK=32. 8 warps = 4(m) x 2(n), warp tile 32x32.
// SMEM stage (padded 80B rows -> ldmatrix conflict-free):
//   Ahi @0 (10240) | Alo @10240 | Bhi @20480 (5120) | Blo @25600 ; stage = 30720.
// Layout: [0,256) bias | stage0 @1024 | stage1 @31744.  Total 62464 B.
#define MSTG 30720
#define GSMEM_BYTES (1024 + 2 * MSTG)   // 62464

#define LOAD_CHUNK(ch) do {                                              \
    uint32_t st = sb + 1024 + ((ch) & 1) * MSTG;                         \
    int kt = (ch) << 5;                                                  \
    _Pragma("unroll")                                                    \
    for (int u = 0; u < 2; ++u) {                                        \
        int idx = tid + (u << 8);                                        \
        int r = idx >> 2, c = idx & 3;                                   \
        uint32_t so = st + r * 80 + c * 16;                              \
        size_t go = (size_t)(mBase + r) * K + kt + c * 8;                \
        cpa16(so, g_Ahi + go);                                           \
        cpa16(so + 10240, g_Alo + go);                                   \
    }                                                                    \
    {                                                                    \
        int r = tid >> 2, c = tid & 3;                                   \
        uint32_t so = st + 20480 + r * 80 + c * 16;                      \
        size_t go = (size_t)(nBase + r) * K + kt + c * 8;                \
        cpa16(so, g_Whi + go);                                           \
        cpa16(so + 5120, g_Wlo + go);                                    \
    }                                                                    \
    asm volatile("cp.async.commit_group;");                              \
} while (0)

__global__ void __launch_bounds__(256, 2)
gemm_mma_kernel(int K, const float* __restrict__ bih, const float* __restrict__ bhh) {
    extern __shared__ __align__(128) char smem[];
    const uint32_t sb = smem_u32(smem);
    float* bsm = (float*)smem;
    int tid = threadIdx.x;
    int lane = tid & 31, warp = tid >> 5;
    int wm = warp >> 1, wn = warp & 1;       // 4 x 2 warp grid
    int nBase = blockIdx.x * 64;
    int mBase = blockIdx.y * 128;

    if (tid < 64) bsm[tid] = bih[nBase + tid] + bhh[nBase + tid];

    float acc[2][4][4];
#pragma unroll
    for (int mt = 0; mt < 2; ++mt)
#pragma unroll
        for (int nt = 0; nt < 4; ++nt)
#pragma unroll
            for (int rg = 0; rg < 4; ++rg) acc[mt][nt][rg] = 0.0f;

    // ldmatrix lane addressing: x4 tile (16 rows x 16 cols b16):
    // lanes 0-15 -> rows 0-15 col+0 ; lanes 16-31 -> rows 0-15 col+16B.
    int lrow = lane & 15;
    int lcolb = (lane >> 4) * 16;

    const int nch = K >> 5;
    LOAD_CHUNK(0);

    for (int ch = 0; ch < nch; ++ch) {
        if (ch + 1 < nch) {
            LOAD_CHUNK(ch + 1);
            asm volatile("cp.async.wait_group 1;" ::: "memory");
        } else {
            asm volatile("cp.async.wait_group 0;" ::: "memory");
        }
        __syncthreads();

        uint32_t st = sb + 1024 + (ch & 1) * MSTG;
        uint32_t aB = st + (wm * 32 + lrow) * 80 + lcolb;
        uint32_t bB = st + 20480 + (wn * 32 + lrow) * 80 + lcolb;

#pragma unroll
        for (int ks = 0; ks < 2; ++ks) {
            int k0b = ks * 32;                      // 16 bf16 = 32 bytes
            uint32_t ah[2][4], al[2][4], bh[2][4], bl[2][4];
#pragma unroll
            for (int mt = 0; mt < 2; ++mt) {
                ldm4(ah[mt], aB + mt * 1280 + k0b);
                ldm4(al[mt], aB + 10240 + mt * 1280 + k0b);
            }
#pragma unroll
            for (int n2 = 0; n2 < 2; ++n2) {
                ldm4(bh[n2], bB + n2 * 1280 + k0b);
                ldm4(bl[n2], bB + 5120 + n2 * 1280 + k0b);
            }
#pragma unroll
            for (int mt = 0; mt < 2; ++mt)
#pragma unroll
                for (int nt = 0; nt < 4; ++nt) {
                    int n2 = nt >> 1, hf = nt & 1;
                    mma_bf16(acc[mt][nt], ah[mt], bh[n2][hf], bh[n2][hf + 2]);
                    mma_bf16(acc[mt][nt], ah[mt], bl[n2][hf], bl[n2][hf + 2]);
                    mma_bf16(acc[mt][nt], al[mt], bh[n2][hf], bh[n2][hf + 2]);
                }
        }
        __syncthreads();
    }

    // epilogue: fold bias, write recurrence layout [s][jgrp][q][jj][b]
#pragma unroll
    for (int mt = 0; mt < 2; ++mt)
#pragma unroll
        for (int nt = 0; nt < 4; ++nt)
#pragma unroll
            for (int rg = 0; rg < 4; ++rg) {
                int m = mBase + wm * 32 + mt * 16 + (lane >> 2) + (rg >> 1) * 8;
                int gl = wn * 32 + nt * 8 + (lane & 3) * 2 + (rg & 1);
                int g = nBase + gl;
                float val = acc[mt][nt][rg] + bsm[gl];
                int s = m >> 5, b = m & 31;
                int q = g >> 10, j1 = g & 1023, jgrp = j1 >> 3, jj = j1 & 7;
                g_xW[(size_t)((s * 128 + jgrp) * 1024 + q * 256 + jj * 32 + b)] = val;
            }
}

// ---------------- persistent recurrence kernel (UNCHANGED from R3-passing) ----------------
#define REC_SMEM (32 * 1024 * 4 + 32 * 33 * 4)

__global__ void __launch_bounds__(256, 1) rec_kernel(int layer, float* __restrict__ dout) {
    extern __shared__ float sm[];
    float* hs = sm;              // [32][1024]
    float* gs = sm + 32768;      // [32][33] padded

    const float4* Wt  = (layer == 0) ? g_Wt2 : (layer == 1) ? g_Wt3 : g_Wt4v;
    const float*  res = (layer == 0) ? (const float*)0 : (layer == 1) ? g_out2 : g_out3;
    float*        out = (layer == 0) ? g_out2 : (layer == 1) ? g_out3 : dout;

    int tid = threadIdx.x, bid = blockIdx.x;
    int r = tid & 31, bgrp = tid >> 5;
    int jj = tid >> 5, bu = tid & 31;
    int nblk = gridDim.x;

    const float4* wp = Wt + (bid * 32 + r);
    const ulonglong2* hp0 = (const ulonglong2*)(hs + (bgrp * 4 + 0) * HID);
    const ulonglong2* hp1 = (const ulonglong2*)(hs + (bgrp * 4 + 1) * HID);
    const ulonglong2* hp2 = (const ulonglong2*)(hs + (bgrp * 4 + 2) * HID);
    const ulonglong2* hp3 = (const ulonglong2*)(hs + (bgrp * 4 + 3) * HID);

    float c = 0.0f;

    for (int t = 0; t < S_LEN; ++t) {
        {
            const float4* gh4 = (const float4*)g_h[t & 1];
            float4* hs4 = (float4*)hs;
#pragma unroll
            for (int i = 0; i < 32; ++i)
                hs4[tid + i * 256] = __ldcg(gh4 + tid + i * 256);
        }
        __syncthreads();

        ull a0 = 0ull, a1 = 0ull, a2 = 0ull, a3 = 0ull;
#pragma unroll 8
        for (int k4 = 0; k4 < 256; ++k4) {
            ulonglong2 w = *(const ulonglong2*)(wp + (size_t)k4 * 4096);
            ulonglong2 x0 = hp0[k4];
            ulonglong2 x1 = hp1[k4];
            ulonglong2 x2 = hp2[k4];
            ulonglong2 x3 = hp3[k4];
            fma2(a0, w.x, x0.x); fma2(a0, w.y, x0.y);
            fma2(a1, w.x, x1.x); fma2(a1, w.y, x1.y);
            fma2(a2, w.x, x2.x); fma2(a2, w.y, x2.y);
            fma2(a3, w.x, x3.x); fma2(a3, w.y, x3.y);
        }
        {
            float2 p;
            p = upk2(a0); gs[(bgrp * 4 + 0) * 33 + r] = p.x + p.y;
            p = upk2(a1); gs[(bgrp * 4 + 1) * 33 + r] = p.x + p.y;
            p = upk2(a2); gs[(bgrp * 4 + 2) * 33 + r] = p.x + p.y;
            p = upk2(a3); gs[(bgrp * 4 + 3) * 33 + r] = p.x + p.y;
        }
        __syncthreads();

        {
            int base = (t * 128 + bid) * 1024 + jj * 32 + bu;
            float gi = gs[bu * 33 + 0 + jj] + g_xW[base];
            float gf = gs[bu * 33 + 8 + jj] + g_xW[base + 256];
            float gg = gs[bu * 33 + 16 + jj] + g_xW[base + 512];
            float go = gs[bu * 33 + 24 + jj] + g_xW[base + 768];
            c = sigm(gf) * c + sigm(gi) * tanhf(gg);
            float h = sigm(go) * tanhf(c);
            int jglob = bid * 8 + jj;
            __stcg(&g_h[(t & 1) ^ 1][bu * HID + jglob], h);
            size_t oidx = (size_t)(t * 32 + bu) * HID + jglob;
            out[oidx] = res ? (h + res[oidx]) : h;
        }
        grid_sync(nblk);
    }
}

// ---------------- output assembly ----------------
__global__ void header_kernel(float* __restrict__ out) {
    int idx = blockIdx.x * 256 + threadIdx.x;
    float v = 0.0f;
    if (idx == 0) v = 513.0f;
    else if (idx == 1) v = 257.0f;
    else if (idx == 2) v = 258.0f;
    else if (idx == 3) v = 513.0f;
    out[idx] = v;
}

__global__ void srccopy_kernel(const float* __restrict__ in, float* __restrict__ out) {
    int idx = blockIdx.x * 256 + threadIdx.x;
    int tt  = idx >> 13;
    int rem = idx & 8191;
    const float4* i4 = (const float4*)in;
    float4* o4 = (float4*)out;
    int b  = rem >> 8;
    int j4 = rem & 255;
    o4[(size_t)(257 + tt) * 8192 + rem] =
        i4[(size_t)(257 + tt) * 16384 + b * 512 + j4];
}

// ---------------- launch ----------------
extern "C" void kernel_launch(void* const* d_in, const int* in_sizes, int n_in,
                              void* d_out, int out_size) {
    const float* input = (const float*)d_in[0];
    const float* Wih2  = (const float*)d_in[1];
    const float* Whh2  = (const float*)d_in[2];
    const float* bih2  = (const float*)d_in[3];
    const float* bhh2  = (const float*)d_in[4];
    const float* Wih3  = (const float*)d_in[5];
    const float* Whh3  = (const float*)d_in[6];
    const float* bih3  = (const float*)d_in[7];
    const float* bhh3  = (const float*)d_in[8];
    const float* Wih4  = (const float*)d_in[9];
    const float* Whh4  = (const float*)d_in[10];
    const float* bih4  = (const float*)d_in[11];
    const float* bhh4  = (const float*)d_in[12];
    const float* mask2 = (const float*)d_in[13];
    const float* mask3 = (const float*)d_in[14];
    float* out = (float*)d_out;

    cudaFuncSetAttribute(rec_kernel, cudaFuncAttributeMaxDynamicSharedMemorySize, REC_SMEM);
    cudaFuncSetAttribute(gemm_mma_kernel, cudaFuncAttributeMaxDynamicSharedMemorySize, GSMEM_BYTES);

    dim3 ggrid(G4 / 64, MROWS / 128);   // (64, 64)

    // ---- layer 2 (gemm_mma is launch index 5 for ncu -s 5) ----
    header_kernel<<<128, 256>>>(out);
    srccopy_kernel<<<8192, 256>>>(input, out);
    convA_kernel<<<16384, 256>>>(0, (const float4*)(input + BATCH * DIN),
                                 (const float4*)0, MROWS * DIN / 4);
    convW_kernel<<<8192, 256>>>((const float4*)Wih2, G4 * DIN / 4);
    wtrans_kernel<<<4096, 256>>>(Whh2, 0);
    gemm_mma_kernel<<<ggrid, 256, GSMEM_BYTES>>>(DIN, bih2, bhh2);
    zeroh_kernel<<<128, 256>>>();
    rec_kernel<<<128, 256, REC_SMEM>>>(0, (float*)0);

    // ---- layer 3 ----
    convA_kernel<<<8192, 256>>>(1, (const float4*)0, (const float4*)mask2, MROWS * HID / 4);
    convW_kernel<<<4096, 256>>>((const float4*)Wih3, G4 * HID / 4);
    wtrans_kernel<<<4096, 256>>>(Whh3, 1);
    gemm_mma_kernel<<<ggrid, 256, GSMEM_BYTES>>>(HID, bih3, bhh3);
    zeroh_kernel<<<128, 256>>>();
    rec_kernel<<<128, 256, REC_SMEM>>>(1, (float*)0);

    // ---- layer 4 ----
    convA_kernel<<<8192, 256>>>(2, (const float4*)0, (const float4*)mask3, MROWS * HID / 4);
    convW_kernel<<<4096, 256>>>((const float4*)Wih4, G4 * HID / 4);
    wtrans_kernel<<<4096, 256>>>(Whh4, 2);
    gemm_mma_kernel<<<ggrid, 256, GSMEM_BYTES>>>(HID, bih4, bhh4);
    zeroh_kernel<<<128, 256>>>();
    rec_kernel<<<128, 256, REC_SMEM>>>(2, out + BATCH * HID);
}